// round 1
// baseline (speedup 1.0000x reference)
#include <cuda_runtime.h>

#define SLEN 256
#define EDIM 128
#define XPAD 132          // padded row stride (floats) -> conflict-free LDS.128
#define NWARP 8
#define QG 4              // queries per warp per iteration
#define NITER (SLEN / (NWARP * QG))   // 8

__global__ void __launch_bounds__(256, 1)
sattn_fp32_kernel(const float* __restrict__ words, const float* __restrict__ Wm,
                  const int* __restrict__ vlen, float* __restrict__ out)
{
    extern __shared__ float sm[];
    float* sx  = sm;                         // [SLEN][XPAD]
    float* sw  = sx + SLEN * XPAD;           // [EDIM][EDIM]
    float* sxw = sw + EDIM * EDIM;           // [NWARP][QG][EDIM]

    const int tid  = threadIdx.x;
    const int lane = tid & 31;
    const int warp = tid >> 5;
    const int sent = blockIdx.x;
    const float* xg = words + (size_t)sent * SLEN * EDIM;

    // ---- load x (row-padded) and W into smem, vectorized ----
    for (int i = tid; i < SLEN * (EDIM / 4); i += 256) {
        float4 v = ((const float4*)xg)[i];
        int r = i >> 5;             // i / (EDIM/4)
        int c = (i & 31) << 2;
        float* d = sx + r * XPAD + c;
        d[0] = v.x; d[1] = v.y; d[2] = v.z; d[3] = v.w;
    }
    for (int i = tid; i < EDIM * EDIM / 4; i += 256)
        ((float4*)sw)[i] = ((const float4*)Wm)[i];
    __syncthreads();

    const int len = vlen[sent];
    float* myxw = sxw + warp * (QG * EDIM);

    for (int it = 0; it < NITER; ++it) {
        const int q0 = (it * NWARP + warp) * QG;

        // ======== phase 1: xw[q0..q0+3][:] = x @ W ========
        // lane owns output columns e = 4*lane .. 4*lane+3
        float a0[QG], a1[QG], a2[QG], a3[QG];
        #pragma unroll
        for (int q = 0; q < QG; ++q) { a0[q] = a1[q] = a2[q] = a3[q] = 0.f; }

        #pragma unroll 4
        for (int k = 0; k < EDIM; ++k) {
            const float4 wv = *(const float4*)(sw + k * EDIM + 4 * lane);
            #pragma unroll
            for (int q = 0; q < QG; ++q) {
                const float xv = sx[(q0 + q) * XPAD + k];     // broadcast
                a0[q] += xv * wv.x; a1[q] += xv * wv.y;
                a2[q] += xv * wv.z; a3[q] += xv * wv.w;
            }
        }
        #pragma unroll
        for (int q = 0; q < QG; ++q) {
            float* d = myxw + q * EDIM + 4 * lane;
            d[0] = a0[q]; d[1] = a1[q]; d[2] = a2[q]; d[3] = a3[q];
        }
        __syncwarp();

        // ======== phase 2: logits[q][t] = xw[q] . x[t],  t = 32*j + lane ========
        float lg[QG][8];
        #pragma unroll
        for (int q = 0; q < QG; ++q)
            #pragma unroll
            for (int j = 0; j < 8; ++j) lg[q][j] = 0.f;

        for (int k0 = 0; k0 < EDIM; k0 += 4) {
            float4 xw4[QG];
            #pragma unroll
            for (int q = 0; q < QG; ++q)
                xw4[q] = *(const float4*)(myxw + q * EDIM + k0);   // broadcast
            #pragma unroll
            for (int j = 0; j < 8; ++j) {
                const int t = j * 32 + lane;
                const float4 xv = *(const float4*)(sx + t * XPAD + k0);
                #pragma unroll
                for (int q = 0; q < QG; ++q) {
                    lg[q][j] += xv.x * xw4[q].x + xv.y * xw4[q].y
                              + xv.z * xw4[q].z + xv.w * xw4[q].w;
                }
            }
        }

        // ======== phase 3: tanh -> exp -> masked renormalized softmax ========
        // reference algebra: p_t = mask_t * e^{l_t} / (sum_mask + 1e-8 * sum_all)
        float sall[QG], smask[QG];
        #pragma unroll
        for (int q = 0; q < QG; ++q) { sall[q] = 0.f; smask[q] = 0.f; }

        #pragma unroll
        for (int j = 0; j < 8; ++j) {
            const int t = j * 32 + lane;
            #pragma unroll
            for (int q = 0; q < QG; ++q) {
                // tanh(x) = 1 - 2/(e^{2x}+1); safe at +/-inf of __expf
                const float e2x = __expf(2.f * lg[q][j]);
                const float th  = 1.f - 2.f / (e2x + 1.f);
                const float w   = __expf(th);
                sall[q] += w;
                const float wm = (t < len) ? w : 0.f;
                smask[q] += wm;
                lg[q][j] = wm;          // reuse: masked weight
            }
        }
        #pragma unroll
        for (int off = 16; off > 0; off >>= 1) {
            #pragma unroll
            for (int q = 0; q < QG; ++q) {
                sall[q]  += __shfl_xor_sync(0xffffffffu, sall[q],  off);
                smask[q] += __shfl_xor_sync(0xffffffffu, smask[q], off);
            }
        }
        float inv[QG];
        #pragma unroll
        for (int q = 0; q < QG; ++q)
            inv[q] = 1.f / (smask[q] + 1e-8f * sall[q]);
        #pragma unroll
        for (int j = 0; j < 8; ++j)
            #pragma unroll
            for (int q = 0; q < QG; ++q)
                lg[q][j] *= inv[q];     // lg now holds p[q][t=32j+lane]

        // ======== phase 4: att[q][e] = sum_t p[q][t] * x[t][e] ========
        float b0[QG], b1[QG], b2[QG], b3[QG];
        #pragma unroll
        for (int q = 0; q < QG; ++q) { b0[q] = b1[q] = b2[q] = b3[q] = 0.f; }

        #pragma unroll
        for (int j = 0; j < 8; ++j) {
            #pragma unroll 8
            for (int s = 0; s < 32; ++s) {
                const int t = j * 32 + s;
                const float4 xv = *(const float4*)(sx + t * XPAD + 4 * lane);
                #pragma unroll
                for (int q = 0; q < QG; ++q) {
                    const float pv = __shfl_sync(0xffffffffu, lg[q][j], s);
                    b0[q] += pv * xv.x; b1[q] += pv * xv.y;
                    b2[q] += pv * xv.z; b3[q] += pv * xv.w;
                }
            }
        }

        // ======== store ========
        #pragma unroll
        for (int q = 0; q < QG; ++q) {
            float4 v; v.x = b0[q]; v.y = b1[q]; v.z = b2[q]; v.w = b3[q];
            *(float4*)(out + ((size_t)sent * SLEN + (q0 + q)) * EDIM + 4 * lane) = v;
        }
    }
}

extern "C" void kernel_launch(void* const* d_in, const int* in_sizes, int n_in,
                              void* d_out, int out_size)
{
    const float* words = (const float*)d_in[0];   // (8,64,256,128) f32
    const float* Wm    = (const float*)d_in[1];   // (128,128) f32
    const int*   vlen  = (const int*)d_in[2];     // (8,64) i32
    float* out = (float*)d_out;

    const size_t smem_bytes =
        (size_t)(SLEN * XPAD + EDIM * EDIM + NWARP * QG * EDIM) * sizeof(float); // 217088

    cudaFuncSetAttribute(sattn_fp32_kernel,
                         cudaFuncAttributeMaxDynamicSharedMemorySize,
                         (int)smem_bytes);

    sattn_fp32_kernel<<<512, 256, smem_bytes>>>(words, Wm, vlen, out);
}

// round 4
// speedup vs baseline: 3.3990x; 3.3990x over previous
#include <cuda_runtime.h>
#include <cuda_bf16.h>
#include <cstdint>

// smem regions (bytes): X hi/lo = 256x128 bf16 (row stride 256B, XOR-swizzled),
// W hi/lo = 128x128 bf16 (stored [k][n], row-major; loaded with ldmatrix.trans)
#define XH_OFF 0
#define XL_OFF 65536
#define WH_OFF 131072
#define WL_OFF 163840
#define SMEM_TOTAL 196608

__device__ __forceinline__ uint32_t smem_u32(const void* p) {
    uint32_t a;
    asm("{ .reg .u64 t; cvta.to.shared.u64 t, %1; cvt.u32.u64 %0, t; }" : "=r"(a) : "l"(p));
    return a;
}
// 16B-chunk XOR swizzle within a 256B row: conflict-free ldmatrix both directions
__device__ __forceinline__ uint32_t soff(uint32_t region, int row, int byte) {
    return region + (uint32_t)(row * 256 + (byte ^ ((row & 7) << 4)));
}
__device__ __forceinline__ void ldsm4(uint32_t addr, uint32_t (&r)[4]) {
    asm volatile("ldmatrix.sync.aligned.m8n8.x4.shared.b16 {%0,%1,%2,%3}, [%4];"
                 : "=r"(r[0]), "=r"(r[1]), "=r"(r[2]), "=r"(r[3]) : "r"(addr));
}
__device__ __forceinline__ void ldsm4t(uint32_t addr, uint32_t (&r)[4]) {
    asm volatile("ldmatrix.sync.aligned.m8n8.x4.trans.shared.b16 {%0,%1,%2,%3}, [%4];"
                 : "=r"(r[0]), "=r"(r[1]), "=r"(r[2]), "=r"(r[3]) : "r"(addr));
}
__device__ __forceinline__ void mma16816(float (&c)[4], const uint32_t (&a)[4],
                                         uint32_t b0, uint32_t b1) {
    asm volatile("mma.sync.aligned.m16n8k16.row.col.f32.bf16.bf16.f32 "
                 "{%0,%1,%2,%3}, {%4,%5,%6,%7}, {%8,%9}, {%0,%1,%2,%3};"
                 : "+f"(c[0]), "+f"(c[1]), "+f"(c[2]), "+f"(c[3])
                 : "r"(a[0]), "r"(a[1]), "r"(a[2]), "r"(a[3]), "r"(b0), "r"(b1));
}
__device__ __forceinline__ uint32_t bpack(float x, float y) {
    __nv_bfloat162 h = __floats2bfloat162_rn(x, y);
    return *reinterpret_cast<uint32_t*>(&h);
}
__device__ __forceinline__ uint32_t bpacklo(float x, float y) {
    float hx = __bfloat162float(__float2bfloat16_rn(x));
    float hy = __bfloat162float(__float2bfloat16_rn(y));
    return bpack(x - hx, y - hy);
}

__global__ void __launch_bounds__(256, 1)
sattn_mma_kernel(const float* __restrict__ words, const float* __restrict__ Wm,
                 const int* __restrict__ vlen, float* __restrict__ out)
{
    extern __shared__ __align__(1024) char smem[];
    const uint32_t sb = smem_u32(smem);
    const int tid = threadIdx.x, lane = tid & 31, warp = tid >> 5;
    const int sent = blockIdx.x >> 1, q0 = (blockIdx.x & 1) * 128;
    const float* xg = words + (size_t)sent * 256 * 128;
    const int len = vlen[sent];

    // ---- load X -> XH/XL (bf16 hi + residual), 8B per thread-iter ----
    for (int i = tid; i < 8192; i += 256) {
        float4 v = ((const float4*)xg)[i];
        int t = i >> 5, b = (i & 31) << 3;           // byte col = e0*2, mult of 8
        uint2 hw, lw;
        hw.x = bpack(v.x, v.y); hw.y = bpack(v.z, v.w);
        lw.x = bpacklo(v.x, v.y); lw.y = bpacklo(v.z, v.w);
        *(uint2*)(smem + soff(XH_OFF, t, b)) = hw;
        *(uint2*)(smem + soff(XL_OFF, t, b)) = lw;
    }
    // ---- load W (row-major [k][n]) -> WH/WL ----
    for (int i = tid; i < 4096; i += 256) {
        float4 v = ((const float4*)Wm)[i];
        int k = i >> 5, b = (i & 31) << 3;
        uint2 hw, lw;
        hw.x = bpack(v.x, v.y); hw.y = bpack(v.z, v.w);
        lw.x = bpacklo(v.x, v.y); lw.y = bpacklo(v.z, v.w);
        *(uint2*)(smem + soff(WH_OFF, k, b)) = hw;
        *(uint2*)(smem + soff(WL_OFF, k, b)) = lw;
    }
    __syncthreads();

    // ================= GEMM1: XW[16 x 128] = Xq @ W (3-pass split) =================
    float xw[16][4];
    #pragma unroll
    for (int j = 0; j < 16; ++j) { xw[j][0] = xw[j][1] = xw[j][2] = xw[j][3] = 0.f; }

    const int r0 = q0 + warp * 16;
    #pragma unroll
    for (int kt = 0; kt < 8; ++kt) {
        uint32_t Ah[4], Al[4];
        {
            int row = r0 + (lane & 15);
            int byt = kt * 32 + ((lane >> 4) << 4);
            ldsm4(sb + soff(XH_OFF, row, byt), Ah);
            ldsm4(sb + soff(XL_OFF, row, byt), Al);
        }
        #pragma unroll
        for (int nn = 0; nn < 8; ++nn) {
            uint32_t Bh[4], Bl[4];
            int rr = kt * 16 + (lane & 7) + (((lane >> 3) & 1) << 3);
            int bb = (nn * 16 + ((lane >> 4) << 3)) * 2;
            ldsm4t(sb + soff(WH_OFF, rr, bb), Bh);
            ldsm4t(sb + soff(WL_OFF, rr, bb), Bl);
            mma16816(xw[2 * nn],     Ah, Bh[0], Bh[1]);
            mma16816(xw[2 * nn + 1], Ah, Bh[2], Bh[3]);
            mma16816(xw[2 * nn],     Ah, Bl[0], Bl[1]);
            mma16816(xw[2 * nn + 1], Ah, Bl[2], Bl[3]);
            mma16816(xw[2 * nn],     Al, Bh[0], Bh[1]);
            mma16816(xw[2 * nn + 1], Al, Bh[2], Bh[3]);
        }
    }

    // ---- accums -> A fragments for GEMM2 (in registers, hi/lo split) ----
    uint32_t ah[8][4], al[8][4];
    #pragma unroll
    for (int kt = 0; kt < 8; ++kt) {
        ah[kt][0] = bpack(xw[2 * kt][0], xw[2 * kt][1]);
        ah[kt][1] = bpack(xw[2 * kt][2], xw[2 * kt][3]);
        ah[kt][2] = bpack(xw[2 * kt + 1][0], xw[2 * kt + 1][1]);
        ah[kt][3] = bpack(xw[2 * kt + 1][2], xw[2 * kt + 1][3]);
        al[kt][0] = bpacklo(xw[2 * kt][0], xw[2 * kt][1]);
        al[kt][1] = bpacklo(xw[2 * kt][2], xw[2 * kt][3]);
        al[kt][2] = bpacklo(xw[2 * kt + 1][0], xw[2 * kt + 1][1]);
        al[kt][3] = bpacklo(xw[2 * kt + 1][2], xw[2 * kt + 1][3]);
    }

    // ================= GEMM2: L[16 x 256] = XW @ X^T (3-pass split) =================
    float la[32][4];
    #pragma unroll
    for (int j = 0; j < 32; ++j) { la[j][0] = la[j][1] = la[j][2] = la[j][3] = 0.f; }

    #pragma unroll
    for (int kt = 0; kt < 8; ++kt) {
        #pragma unroll
        for (int nn = 0; nn < 16; ++nn) {
            uint32_t Bh[4], Bl[4];
            int rr = nn * 16 + (lane & 7) + ((lane >> 4) << 3);
            int bb = kt * 32 + (((lane >> 3) & 1) << 4);
            ldsm4(sb + soff(XH_OFF, rr, bb), Bh);
            ldsm4(sb + soff(XL_OFF, rr, bb), Bl);
            mma16816(la[2 * nn],     ah[kt], Bh[0], Bh[1]);
            mma16816(la[2 * nn + 1], ah[kt], Bh[2], Bh[3]);
            mma16816(la[2 * nn],     ah[kt], Bl[0], Bl[1]);
            mma16816(la[2 * nn + 1], ah[kt], Bl[2], Bl[3]);
            mma16816(la[2 * nn],     al[kt], Bh[0], Bh[1]);
            mma16816(la[2 * nn + 1], al[kt], Bh[2], Bh[3]);
        }
    }

    // ================= softmax (rows g = lane/4 and g+8; cols t) =================
    float sa0 = 0.f, sm0 = 0.f, sa1 = 0.f, sm1 = 0.f;
    #pragma unroll
    for (int j = 0; j < 32; ++j) {
        int tb = 8 * j + 2 * (lane & 3);
        #pragma unroll
        for (int c = 0; c < 2; ++c) {
            const bool m = (tb + c) < len;
            // row g
            {
                float l = la[j][c];
                float u = __expf(2.f * l);
                float th = 1.f - __fdividef(2.f, u + 1.f);
                float w = __expf(th);
                float wm = m ? w : 0.f;
                sa0 += w; sm0 += wm; la[j][c] = wm;
            }
            // row g+8
            {
                float l = la[j][2 + c];
                float u = __expf(2.f * l);
                float th = 1.f - __fdividef(2.f, u + 1.f);
                float w = __expf(th);
                float wm = m ? w : 0.f;
                sa1 += w; sm1 += wm; la[j][2 + c] = wm;
            }
        }
    }
    #pragma unroll
    for (int off = 1; off <= 2; off <<= 1) {
        sa0 += __shfl_xor_sync(0xffffffffu, sa0, off);
        sm0 += __shfl_xor_sync(0xffffffffu, sm0, off);
        sa1 += __shfl_xor_sync(0xffffffffu, sa1, off);
        sm1 += __shfl_xor_sync(0xffffffffu, sm1, off);
    }
    const float inv0 = 1.f / (sm0 + 1e-8f * sa0);
    const float inv1 = 1.f / (sm1 + 1e-8f * sa1);
    #pragma unroll
    for (int j = 0; j < 32; ++j) {
        la[j][0] *= inv0; la[j][1] *= inv0;
        la[j][2] *= inv1; la[j][3] *= inv1;
    }

    // ---- P accums -> A fragments for GEMM3 (hi/lo split, replaces la) ----
    uint32_t ph[16][4], pl[16][4];
    #pragma unroll
    for (int kt = 0; kt < 16; ++kt) {
        ph[kt][0] = bpack(la[2 * kt][0], la[2 * kt][1]);
        ph[kt][1] = bpack(la[2 * kt][2], la[2 * kt][3]);
        ph[kt][2] = bpack(la[2 * kt + 1][0], la[2 * kt + 1][1]);
        ph[kt][3] = bpack(la[2 * kt + 1][2], la[2 * kt + 1][3]);
        pl[kt][0] = bpacklo(la[2 * kt][0], la[2 * kt][1]);
        pl[kt][1] = bpacklo(la[2 * kt][2], la[2 * kt][3]);
        pl[kt][2] = bpacklo(la[2 * kt + 1][0], la[2 * kt + 1][1]);
        pl[kt][3] = bpacklo(la[2 * kt + 1][2], la[2 * kt + 1][3]);
    }

    // ================= GEMM3: att[16 x 128] = P @ X (3-pass split) =================
    float oa[16][4];
    #pragma unroll
    for (int j = 0; j < 16; ++j) { oa[j][0] = oa[j][1] = oa[j][2] = oa[j][3] = 0.f; }

    #pragma unroll
    for (int kt = 0; kt < 16; ++kt) {
        #pragma unroll
        for (int nn = 0; nn < 8; ++nn) {
            uint32_t Bh[4], Bl[4];
            int rr = kt * 16 + (lane & 7) + (((lane >> 3) & 1) << 3);
            int bb = (nn * 16 + ((lane >> 4) << 3)) * 2;
            ldsm4t(sb + soff(XH_OFF, rr, bb), Bh);
            ldsm4t(sb + soff(XL_OFF, rr, bb), Bl);
            mma16816(oa[2 * nn],     ph[kt], Bh[0], Bh[1]);
            mma16816(oa[2 * nn + 1], ph[kt], Bh[2], Bh[3]);
            mma16816(oa[2 * nn],     ph[kt], Bl[0], Bl[1]);
            mma16816(oa[2 * nn + 1], ph[kt], Bl[2], Bl[3]);
            mma16816(oa[2 * nn],     pl[kt], Bh[0], Bh[1]);
            mma16816(oa[2 * nn + 1], pl[kt], Bh[2], Bh[3]);
        }
    }

    // ================= store (f32) =================
    {
        const int g = lane >> 2, q = lane & 3;
        const size_t rbase = (size_t)sent * 256 + q0 + warp * 16;
        #pragma unroll
        for (int j = 0; j < 16; ++j) {
            int col = 8 * j + 2 * q;
            float2 v0; v0.x = oa[j][0]; v0.y = oa[j][1];
            float2 v1; v1.x = oa[j][2]; v1.y = oa[j][3];
            *(float2*)(out + (rbase + g) * 128 + col) = v0;
            *(float2*)(out + (rbase + g + 8) * 128 + col) = v1;
        }
    }
}

extern "C" void kernel_launch(void* const* d_in, const int* in_sizes, int n_in,
                              void* d_out, int out_size)
{
    const float* words = (const float*)d_in[0];
    const float* Wm    = (const float*)d_in[1];
    const int*   vlen  = (const int*)d_in[2];
    float* out = (float*)d_out;

    cudaFuncSetAttribute(sattn_mma_kernel,
                         cudaFuncAttributeMaxDynamicSharedMemorySize, SMEM_TOTAL);
    sattn_mma_kernel<<<1024, 256, SMEM_TOTAL>>>(words, Wm, vlen, out);
}

// round 5
// speedup vs baseline: 3.4000x; 1.0003x over previous
#include <cuda_runtime.h>
#include <cuda_bf16.h>
#include <cstdint>

// smem regions (bytes): X hi/lo = 256x128 bf16 (row stride 256B, XOR-swizzled),
// W hi/lo = 128x128 bf16 ([k][n]); after GEMM1 the W regions are reused as XW hi/lo.
#define XH_OFF 0
#define XL_OFF 65536
#define WH_OFF 131072
#define WL_OFF 163840
#define SMEM_TOTAL 196608

__device__ __forceinline__ uint32_t smem_u32(const void* p) {
    uint32_t a;
    asm("{ .reg .u64 t; cvta.to.shared.u64 t, %1; cvt.u32.u64 %0, t; }" : "=r"(a) : "l"(p));
    return a;
}
// 16B-chunk XOR swizzle within a 256B row: conflict-free ldmatrix both directions
__device__ __forceinline__ uint32_t soff(uint32_t region, int row, int byte) {
    return region + (uint32_t)(row * 256 + (byte ^ ((row & 7) << 4)));
}
__device__ __forceinline__ void ldsm4(uint32_t addr, uint32_t (&r)[4]) {
    asm volatile("ldmatrix.sync.aligned.m8n8.x4.shared.b16 {%0,%1,%2,%3}, [%4];"
                 : "=r"(r[0]), "=r"(r[1]), "=r"(r[2]), "=r"(r[3]) : "r"(addr));
}
__device__ __forceinline__ void ldsm4t(uint32_t addr, uint32_t (&r)[4]) {
    asm volatile("ldmatrix.sync.aligned.m8n8.x4.trans.shared.b16 {%0,%1,%2,%3}, [%4];"
                 : "=r"(r[0]), "=r"(r[1]), "=r"(r[2]), "=r"(r[3]) : "r"(addr));
}
__device__ __forceinline__ void mma16816(float (&c)[4], const uint32_t (&a)[4],
                                         uint32_t b0, uint32_t b1) {
    asm volatile("mma.sync.aligned.m16n8k16.row.col.f32.bf16.bf16.f32 "
                 "{%0,%1,%2,%3}, {%4,%5,%6,%7}, {%8,%9}, {%0,%1,%2,%3};"
                 : "+f"(c[0]), "+f"(c[1]), "+f"(c[2]), "+f"(c[3])
                 : "r"(a[0]), "r"(a[1]), "r"(a[2]), "r"(a[3]), "r"(b0), "r"(b1));
}
__device__ __forceinline__ uint32_t bpack(float x, float y) {
    __nv_bfloat162 h = __floats2bfloat162_rn(x, y);
    return *reinterpret_cast<uint32_t*>(&h);
}
__device__ __forceinline__ uint32_t bpacklo(float x, float y) {
    float hx = __bfloat162float(__float2bfloat16_rn(x));
    float hy = __bfloat162float(__float2bfloat16_rn(y));
    return bpack(x - hx, y - hy);
}

__global__ void __launch_bounds__(256, 1)
sattn_mma_kernel(const float* __restrict__ words, const float* __restrict__ Wm,
                 const int* __restrict__ vlen, float* __restrict__ out)
{
    extern __shared__ __align__(1024) char smem[];
    const uint32_t sb = smem_u32(smem);
    const int tid = threadIdx.x, lane = tid & 31, warp = tid >> 5;
    const int sent = blockIdx.x >> 1, q0 = (blockIdx.x & 1) * 128;
    const float* xg = words + (size_t)sent * 256 * 128;
    const int len = vlen[sent];

    // ---- load X -> XH/XL (bf16 hi + residual) ----
    for (int i = tid; i < 8192; i += 256) {
        float4 v = ((const float4*)xg)[i];
        int t = i >> 5, b = (i & 31) << 3;
        uint2 hw, lw;
        hw.x = bpack(v.x, v.y); hw.y = bpack(v.z, v.w);
        lw.x = bpacklo(v.x, v.y); lw.y = bpacklo(v.z, v.w);
        *(uint2*)(smem + soff(XH_OFF, t, b)) = hw;
        *(uint2*)(smem + soff(XL_OFF, t, b)) = lw;
    }
    // ---- load W (row-major [k][n]) -> WH/WL ----
    for (int i = tid; i < 4096; i += 256) {
        float4 v = ((const float4*)Wm)[i];
        int k = i >> 5, b = (i & 31) << 3;
        uint2 hw, lw;
        hw.x = bpack(v.x, v.y); hw.y = bpack(v.z, v.w);
        lw.x = bpacklo(v.x, v.y); lw.y = bpacklo(v.z, v.w);
        *(uint2*)(smem + soff(WH_OFF, k, b)) = hw;
        *(uint2*)(smem + soff(WL_OFF, k, b)) = lw;
    }
    __syncthreads();

    const int r0 = q0 + warp * 16;
    const int g = lane >> 2, q4 = lane & 3;

    // ================= GEMM1: XW[16 x 128] = Xq @ W (3-pass split) =================
    {
        float xw[16][4];
        #pragma unroll
        for (int j = 0; j < 16; ++j) { xw[j][0] = xw[j][1] = xw[j][2] = xw[j][3] = 0.f; }

        #pragma unroll
        for (int kt = 0; kt < 8; ++kt) {
            uint32_t Ah[4], Al[4];
            {
                int row = r0 + (lane & 15);
                int byt = kt * 32 + ((lane >> 4) << 4);
                ldsm4(sb + soff(XH_OFF, row, byt), Ah);
                ldsm4(sb + soff(XL_OFF, row, byt), Al);
            }
            #pragma unroll
            for (int nn = 0; nn < 8; ++nn) {
                uint32_t Bh[4], Bl[4];
                int rr = kt * 16 + (lane & 7) + (((lane >> 3) & 1) << 3);
                int bb = (nn * 16 + ((lane >> 4) << 3)) * 2;
                ldsm4t(sb + soff(WH_OFF, rr, bb), Bh);
                ldsm4t(sb + soff(WL_OFF, rr, bb), Bl);
                mma16816(xw[2 * nn],     Ah, Bh[0], Bh[1]);
                mma16816(xw[2 * nn + 1], Ah, Bh[2], Bh[3]);
                mma16816(xw[2 * nn],     Ah, Bl[0], Bl[1]);
                mma16816(xw[2 * nn + 1], Ah, Bl[2], Bl[3]);
                mma16816(xw[2 * nn],     Al, Bh[0], Bh[1]);
                mma16816(xw[2 * nn + 1], Al, Bh[2], Bh[3]);
            }
        }
        __syncthreads();   // everyone done reading W before we overwrite it

        // ---- store XW hi/lo into W region (rows are warp-private) ----
        #pragma unroll
        for (int j = 0; j < 16; ++j) {
            int nbyte = 2 * (8 * j + 2 * q4);
            *(uint32_t*)(smem + soff(WH_OFF, warp * 16 + g,     nbyte)) = bpack(xw[j][0], xw[j][1]);
            *(uint32_t*)(smem + soff(WL_OFF, warp * 16 + g,     nbyte)) = bpacklo(xw[j][0], xw[j][1]);
            *(uint32_t*)(smem + soff(WH_OFF, warp * 16 + g + 8, nbyte)) = bpack(xw[j][2], xw[j][3]);
            *(uint32_t*)(smem + soff(WL_OFF, warp * 16 + g + 8, nbyte)) = bpacklo(xw[j][2], xw[j][3]);
        }
        __syncwarp();
    }

    // ======= per 128-key half: GEMM2 -> exp/mask -> partial GEMM3 (unnormalized) =======
    float oa[16][4];
    #pragma unroll
    for (int j = 0; j < 16; ++j) { oa[j][0] = oa[j][1] = oa[j][2] = oa[j][3] = 0.f; }
    float sa0 = 0.f, sm0 = 0.f, sa1 = 0.f, sm1 = 0.f;

    #pragma unroll
    for (int th = 0; th < 2; ++th) {
        float la[16][4];
        #pragma unroll
        for (int j = 0; j < 16; ++j) { la[j][0] = la[j][1] = la[j][2] = la[j][3] = 0.f; }

        // ---- GEMM2 half: L[16 x 128] = XW @ X^T ----
        #pragma unroll
        for (int kt = 0; kt < 8; ++kt) {
            uint32_t Ah[4], Al[4];
            {
                int row = warp * 16 + (lane & 15);
                int byt = kt * 32 + ((lane >> 4) << 4);
                ldsm4(sb + soff(WH_OFF, row, byt), Ah);
                ldsm4(sb + soff(WL_OFF, row, byt), Al);
            }
            #pragma unroll
            for (int nn = 0; nn < 8; ++nn) {
                uint32_t Bh[4], Bl[4];
                int rr = th * 128 + nn * 16 + (lane & 7) + ((lane >> 4) << 3);
                int bb = kt * 32 + (((lane >> 3) & 1) << 4);
                ldsm4(sb + soff(XH_OFF, rr, bb), Bh);
                ldsm4(sb + soff(XL_OFF, rr, bb), Bl);
                mma16816(la[2 * nn],     Ah, Bh[0], Bh[1]);
                mma16816(la[2 * nn + 1], Ah, Bh[2], Bh[3]);
                mma16816(la[2 * nn],     Ah, Bl[0], Bl[1]);
                mma16816(la[2 * nn + 1], Ah, Bl[2], Bl[3]);
                mma16816(la[2 * nn],     Al, Bh[0], Bh[1]);
                mma16816(la[2 * nn + 1], Al, Bh[2], Bh[3]);
            }
        }

        // ---- tanh -> exp -> mask (keep UNNORMALIZED w; row sums accumulated) ----
        #pragma unroll
        for (int j = 0; j < 16; ++j) {
            int tb = th * 128 + 8 * j + 2 * q4;
            #pragma unroll
            for (int c = 0; c < 2; ++c) {
                const bool m = (tb + c) < len;
                {
                    float l = la[j][c];
                    float u = __expf(2.f * l);
                    float t2 = 1.f - __fdividef(2.f, u + 1.f);
                    float w = __expf(t2);
                    float wm = m ? w : 0.f;
                    sa0 += w; sm0 += wm; la[j][c] = wm;
                }
                {
                    float l = la[j][2 + c];
                    float u = __expf(2.f * l);
                    float t2 = 1.f - __fdividef(2.f, u + 1.f);
                    float w = __expf(t2);
                    float wm = m ? w : 0.f;
                    sa1 += w; sm1 += wm; la[j][2 + c] = wm;
                }
            }
        }

        // ---- GEMM3 partial: oa += w_half @ X_half (packs built on the fly) ----
        #pragma unroll
        for (int kt = 0; kt < 8; ++kt) {
            uint32_t ph[4], pl[4];
            ph[0] = bpack(la[2 * kt][0], la[2 * kt][1]);
            ph[1] = bpack(la[2 * kt][2], la[2 * kt][3]);
            ph[2] = bpack(la[2 * kt + 1][0], la[2 * kt + 1][1]);
            ph[3] = bpack(la[2 * kt + 1][2], la[2 * kt + 1][3]);
            pl[0] = bpacklo(la[2 * kt][0], la[2 * kt][1]);
            pl[1] = bpacklo(la[2 * kt][2], la[2 * kt][3]);
            pl[2] = bpacklo(la[2 * kt + 1][0], la[2 * kt + 1][1]);
            pl[3] = bpacklo(la[2 * kt + 1][2], la[2 * kt + 1][3]);
            #pragma unroll
            for (int nn = 0; nn < 8; ++nn) {
                uint32_t Bh[4], Bl[4];
                int rr = th * 128 + kt * 16 + (lane & 7) + (((lane >> 3) & 1) << 3);
                int bb = (nn * 16 + ((lane >> 4) << 3)) * 2;
                ldsm4t(sb + soff(XH_OFF, rr, bb), Bh);
                ldsm4t(sb + soff(XL_OFF, rr, bb), Bl);
                mma16816(oa[2 * nn],     ph, Bh[0], Bh[1]);
                mma16816(oa[2 * nn + 1], ph, Bh[2], Bh[3]);
                mma16816(oa[2 * nn],     ph, Bl[0], Bl[1]);
                mma16816(oa[2 * nn + 1], ph, Bl[2], Bl[3]);
                mma16816(oa[2 * nn],     pl, Bh[0], Bh[1]);
                mma16816(oa[2 * nn + 1], pl, Bh[2], Bh[3]);
            }
        }
    }

    // ================= row sums -> inverse -> scale -> store =================
    #pragma unroll
    for (int off = 1; off <= 2; off <<= 1) {
        sa0 += __shfl_xor_sync(0xffffffffu, sa0, off);
        sm0 += __shfl_xor_sync(0xffffffffu, sm0, off);
        sa1 += __shfl_xor_sync(0xffffffffu, sa1, off);
        sm1 += __shfl_xor_sync(0xffffffffu, sm1, off);
    }
    const float inv0 = 1.f / (sm0 + 1e-8f * sa0);
    const float inv1 = 1.f / (sm1 + 1e-8f * sa1);

    {
        const size_t rbase = (size_t)sent * 256 + r0;
        #pragma unroll
        for (int j = 0; j < 16; ++j) {
            int col = 8 * j + 2 * q4;
            float2 v0; v0.x = oa[j][0] * inv0; v0.y = oa[j][1] * inv0;
            float2 v1; v1.x = oa[j][2] * inv1; v1.y = oa[j][3] * inv1;
            *(float2*)(out + (rbase + g) * 128 + col) = v0;
            *(float2*)(out + (rbase + g + 8) * 128 + col) = v1;
        }
    }
}

extern "C" void kernel_launch(void* const* d_in, const int* in_sizes, int n_in,
                              void* d_out, int out_size)
{
    const float* words = (const float*)d_in[0];
    const float* Wm    = (const float*)d_in[1];
    const int*   vlen  = (const int*)d_in[2];
    float* out = (float*)d_out;

    cudaFuncSetAttribute(sattn_mma_kernel,
                         cudaFuncAttributeMaxDynamicSharedMemorySize, SMEM_TOTAL);
    sattn_mma_kernel<<<1024, 256, SMEM_TOTAL>>>(words, Wm, vlen, out);
}